// round 1
// baseline (speedup 1.0000x reference)
#include <cuda_runtime.h>
#include <cstdint>

// Problem constants
static constexpr int Bb = 2048, Tt = 281, Kk = 272, Nn = 272;

// Tiling
#define THREADS 192
static constexpr int BM = 96, BN = 96, BK = 16;
static constexpr int STAGES = 3;
static constexpr int XPAD = 20;   // sX row stride (floats): conflict-free A-frag reads
static constexpr int WPAD = 104;  // sW row stride (floats): conflict-free B-frag reads
static constexpr int KITERS = Kk / BK;  // 17, exact

// subject dtype flag: 1 if int64, 0 if int32 (jax may demote int64 -> int32)
__device__ int g_subj_is64;

__global__ void probe_subject_kernel(const unsigned int* subj_words) {
    if (threadIdx.x == 0 && blockIdx.x == 0) {
        // If int64: words at odd indices are the (zero) high halves of values in [0,4).
        // If int32: odd-index words are random subjects in [0,4) -> virtually surely nonzero somewhere.
        // Reading 2048 words = 8KB is in-bounds for both layouts.
        int is64 = 1;
        for (int i = 1; i < 2048; i += 2) {
            if (subj_words[i] != 0u) { is64 = 0; break; }
        }
        g_subj_is64 = is64;
    }
}

__device__ __forceinline__ uint32_t f2tf32(float f) {
    uint32_t u;
    asm("cvt.rna.tf32.f32 %0, %1;" : "=r"(u) : "f"(f));
    return u;
}

__device__ __forceinline__ void mma_tf32(float* d, const uint32_t* a, const uint32_t* bfr) {
    asm volatile(
        "mma.sync.aligned.m16n8k8.row.col.f32.tf32.tf32.f32 "
        "{%0,%1,%2,%3}, {%4,%5,%6,%7}, {%8,%9}, {%0,%1,%2,%3};"
        : "+f"(d[0]), "+f"(d[1]), "+f"(d[2]), "+f"(d[3])
        : "r"(a[0]), "r"(a[1]), "r"(a[2]), "r"(a[3]), "r"(bfr[0]), "r"(bfr[1]));
}

__device__ __forceinline__ void cp_async16(uint32_t dst, const void* src, int sz) {
    asm volatile("cp.async.cg.shared.global [%0], [%1], 16, %2;\n"
                 :: "r"(dst), "l"(src), "r"(sz));
}

__global__ __launch_bounds__(THREADS) void subj_gemm_kernel(
    const float* __restrict__ X, const void* __restrict__ subj,
    const float* __restrict__ W, const float* __restrict__ bias,
    float* __restrict__ out)
{
    __shared__ float sX[STAGES][BM][XPAD];
    __shared__ float sW[STAGES][BK][WPAD];

    const int b  = blockIdx.z;
    const int m0 = blockIdx.y * BM;
    const int n0 = blockIdx.x * BN;

    int s;
    if (g_subj_is64) s = (int)((const long long*)subj)[b];
    else             s = ((const int*)subj)[b];

    const float* Xb = X + (size_t)b * Tt * Kk;
    const float* Ws = W + (size_t)s * Kk * Nn;

    const int tid  = threadIdx.x;
    const int lane = tid & 31;
    const int warp = tid >> 5;     // 0..5
    const int wm   = warp / 3;     // 0..1  (warp-tile rows of 48)
    const int wn   = warp % 3;     // 0..2  (warp-tile cols of 32)
    const int gid  = lane >> 2;    // 0..7
    const int tig  = lane & 3;     // 0..3

    float acc[3][4][4];
#pragma unroll
    for (int i = 0; i < 3; ++i)
#pragma unroll
        for (int j = 0; j < 4; ++j)
#pragma unroll
            for (int k = 0; k < 4; ++k) acc[i][j][k] = 0.f;

    // ---- async stage loader: X tile [BM x BK], W tile [BK x BN], 16B chunks ----
    auto load_stage = [&](int st, int k0) {
        // X: 96 rows x 4 chunks = 384 tasks, 2 per thread
#pragma unroll
        for (int it = 0; it < 2; ++it) {
            int i   = tid + it * THREADS;
            int row = i >> 2;
            int ch  = (i & 3) << 2;         // float offset in row
            int t   = m0 + row;
            bool v  = (t < Tt);
            const float* src = Xb + (size_t)(v ? t : (Tt - 1)) * Kk + k0 + ch;
            uint32_t dst = (uint32_t)__cvta_generic_to_shared(&sX[st][row][ch]);
            cp_async16(dst, src, v ? 16 : 0);
        }
        // W: 16 rows x 24 chunks = 384 tasks, 2 per thread
#pragma unroll
        for (int it = 0; it < 2; ++it) {
            int i   = tid + it * THREADS;
            int row = i / 24;
            int ch  = (i % 24) << 2;
            int n   = n0 + ch;
            bool v  = (n < Nn);
            const float* src = Ws + (size_t)(k0 + row) * Nn + (v ? n : (Nn - 4));
            uint32_t dst = (uint32_t)__cvta_generic_to_shared(&sW[st][row][ch]);
            cp_async16(dst, src, v ? 16 : 0);
        }
    };

    // Prologue: fill first STAGES-1 stages
    load_stage(0, 0);
    asm volatile("cp.async.commit_group;" ::: "memory");
    load_stage(1, BK);
    asm volatile("cp.async.commit_group;" ::: "memory");

    for (int kk = 0; kk < KITERS; ++kk) {
        asm volatile("cp.async.wait_group 1;" ::: "memory");
        __syncthreads();

        // Issue next stage load (into the slot freed by iteration kk-1; safe after the sync)
        int kn = kk + 2;
        if (kn < KITERS) load_stage(kn % STAGES, kn * BK);
        asm volatile("cp.async.commit_group;" ::: "memory");  // commit even when empty: keeps group accounting exact

        const int st = kk % STAGES;
#pragma unroll
        for (int ks = 0; ks < 2; ++ks) {          // two k8 steps per BK=16
            const int kb = ks * 8;

            uint32_t af[3][4];
#pragma unroll
            for (int mi = 0; mi < 3; ++mi) {
                int r = wm * 48 + mi * 16 + gid;
                af[mi][0] = f2tf32(sX[st][r    ][kb + tig    ]);
                af[mi][1] = f2tf32(sX[st][r + 8][kb + tig    ]);
                af[mi][2] = f2tf32(sX[st][r    ][kb + tig + 4]);
                af[mi][3] = f2tf32(sX[st][r + 8][kb + tig + 4]);
            }
            uint32_t bf[4][2];
#pragma unroll
            for (int ni = 0; ni < 4; ++ni) {
                int c = wn * 32 + ni * 8 + gid;
                bf[ni][0] = f2tf32(sW[st][kb + tig    ][c]);
                bf[ni][1] = f2tf32(sW[st][kb + tig + 4][c]);
            }
#pragma unroll
            for (int mi = 0; mi < 3; ++mi)
#pragma unroll
                for (int ni = 0; ni < 4; ++ni)
                    mma_tf32(acc[mi][ni], af[mi], bf[ni]);
        }
    }

    // ---- epilogue: bias add + guarded float2 stores ----
    float* outb = out + (size_t)b * Tt * Nn;
#pragma unroll
    for (int mi = 0; mi < 3; ++mi) {
        int r0 = m0 + wm * 48 + mi * 16 + gid;
#pragma unroll
        for (int ni = 0; ni < 4; ++ni) {
            int n = n0 + wn * 32 + ni * 8 + tig * 2;
            if (n < Nn) {   // n even, Nn even -> n+1 also valid
                float bv0 = bias[s * Nn + n];
                float bv1 = bias[s * Nn + n + 1];
                if (r0 < Tt) {
                    float2 v = make_float2(acc[mi][ni][0] + bv0, acc[mi][ni][1] + bv1);
                    *reinterpret_cast<float2*>(outb + (size_t)r0 * Nn + n) = v;
                }
                if (r0 + 8 < Tt) {
                    float2 v = make_float2(acc[mi][ni][2] + bv0, acc[mi][ni][3] + bv1);
                    *reinterpret_cast<float2*>(outb + (size_t)(r0 + 8) * Nn + n) = v;
                }
            }
        }
    }
}

extern "C" void kernel_launch(void* const* d_in, const int* in_sizes, int n_in,
                              void* d_out, int out_size) {
    const float* X    = (const float*)d_in[0];
    const void*  subj = d_in[1];
    const float* W    = (const float*)d_in[2];
    const float* bias = (const float*)d_in[3];
    float* out = (float*)d_out;

    probe_subject_kernel<<<1, 32>>>((const unsigned int*)subj);

    dim3 grid((Nn + BN - 1) / BN,   // 3
              (Tt + BM - 1) / BM,   // 3
              Bb);                  // 2048
    subj_gemm_kernel<<<grid, dim3(THREADS)>>>(X, subj, W, bias, out);
}

// round 3
// speedup vs baseline: 1.0052x; 1.0052x over previous
#include <cuda_runtime.h>
#include <cstdint>

// Problem constants
static constexpr int Bb = 2048, Tt = 281, Kk = 272, Nn = 272;

#define THREADS 192
static constexpr int BM = 96, BN = 96, BK = 16;
static constexpr int STAGES = 3;
static constexpr int XSTR = 20;          // sX row stride (floats): conflict-free + 16B aligned
static constexpr int KITERS = Kk / BK;   // 17, exact
static constexpr int NKB = Kk / 8;       // 34 k8-chunks
static constexpr int NNB = Nn / 8;       // 34 n8-blocks
static constexpr int NBL = BN / 8;       // 12 n-blocks per CTA

// Fragment-ordered, RNA-pre-rounded weights:
// g_Wf[((e*NNB + nb)*NKB + kc)*64 + lane*2 + {0,1}] = rna(W[e][kc*8+tig+{0,4}][nb*8+gid])
__device__ float g_Wf[4 * NNB * NKB * 64];

// subject dtype flag: 1 if int64, 0 if int32 (jax may demote int64 -> int32)
__device__ int g_subj_is64;

__global__ void probe_subject_kernel(const unsigned int* subj_words) {
    if (threadIdx.x == 0 && blockIdx.x == 0) {
        int is64 = 1;
        for (int i = 1; i < 2048; i += 2)
            if (subj_words[i] != 0u) { is64 = 0; break; }
        g_subj_is64 = is64;
    }
}

__device__ __forceinline__ uint32_t f2tf32(float f) {
    uint32_t u;
    asm("cvt.rna.tf32.f32 %0, %1;" : "=r"(u) : "f"(f));
    return u;
}

// One-time W -> fragment-ordered tf32(RNA) layout
__global__ void prep_w_frag(const float* __restrict__ W) {
    int idx = blockIdx.x * blockDim.x + threadIdx.x;
    if (idx >= 4 * NNB * NKB * 32) return;
    int lane = idx & 31;
    int kc   = (idx >> 5) % NKB;
    int nb   = ((idx >> 5) / NKB) % NNB;
    int e    = (idx >> 5) / (NKB * NNB);
    int gid = lane >> 2, tig = lane & 3;
    int n  = nb * 8 + gid;
    int k0 = kc * 8 + tig;
    const float* We = W + (size_t)e * Kk * Nn;
    float2 v;
    v.x = __uint_as_float(f2tf32(We[(size_t)k0 * Nn + n]));
    v.y = __uint_as_float(f2tf32(We[(size_t)(k0 + 4) * Nn + n]));
    *reinterpret_cast<float2*>(
        &g_Wf[(((size_t)(e * NNB + nb) * NKB + kc) * 32 + lane) * 2]) = v;
}

__device__ __forceinline__ void mma_tf32(float* d, const uint32_t* a, const uint32_t* bfr) {
    asm volatile(
        "mma.sync.aligned.m16n8k8.row.col.f32.tf32.tf32.f32 "
        "{%0,%1,%2,%3}, {%4,%5,%6,%7}, {%8,%9}, {%0,%1,%2,%3};"
        : "+f"(d[0]), "+f"(d[1]), "+f"(d[2]), "+f"(d[3])
        : "r"(a[0]), "r"(a[1]), "r"(a[2]), "r"(a[3]), "r"(bfr[0]), "r"(bfr[1]));
}

__device__ __forceinline__ void cp_async16(uint32_t dst, const void* src, int sz) {
    asm volatile("cp.async.cg.shared.global [%0], [%1], 16, %2;\n"
                 :: "r"(dst), "l"(src), "r"(sz));
}

__global__ __launch_bounds__(THREADS) void subj_gemm_kernel(
    const float* __restrict__ X, const void* __restrict__ subj,
    const float* __restrict__ bias, float* __restrict__ out)
{
    // X tiles: tf32-bits, row-major, stride 20 floats
    __shared__ float sX[STAGES][BM][XSTR];
    // W tiles: fragment-major: [(nbl*2 + ks)*64 + lane*2 + {0,1}]
    __shared__ float sW[STAGES][NBL * 2 * 64];

    const int b  = blockIdx.z;
    const int m0 = blockIdx.y * BM;
    const int nb0 = blockIdx.x * NBL;    // n-block origin
    const int n0  = nb0 * 8;

    int s;
    if (g_subj_is64) s = (int)((const long long*)subj)[b];
    else             s = ((const int*)subj)[b];

    const float* Xb  = X + (size_t)b * Tt * Kk;
    const float* Wfe = g_Wf + (size_t)s * NNB * NKB * 64;

    const int tid  = threadIdx.x;
    const int lane = tid & 31;
    const int warp = tid >> 5;     // 0..5
    const int wm   = warp / 3;     // 0..1  (warp rows of 48)
    const int wn   = warp % 3;     // 0..2  (warp cols of 32 = 4 n-blocks)
    const int gid  = lane >> 2;    // 0..7
    const int tig  = lane & 3;     // 0..3

    float acc[3][4][4];
#pragma unroll
    for (int i = 0; i < 3; ++i)
#pragma unroll
        for (int j = 0; j < 4; ++j)
#pragma unroll
            for (int k = 0; k < 4; ++k) acc[i][j][k] = 0.f;

    // ---- stage loader ----
    // X: LDG.128 -> rna cvt -> STS.128 (96 rows x 4 float4 = 384 tasks, 2/thread)
    // W: cp.async 16B from fragment-ordered gmem (384 chunks, 2/thread)
    auto load_stage = [&](int st, int ci) {
        const int k0  = ci * BK;
        const int kc0 = ci * 2;
#pragma unroll
        for (int it = 0; it < 2; ++it) {
            int t   = tid + it * THREADS;
            int row = t >> 2;
            int j   = t & 3;
            int m   = m0 + row;
            int mc  = (m < Tt) ? m : (Tt - 1);
            float4 v = *reinterpret_cast<const float4*>(Xb + (size_t)mc * Kk + k0 + 4 * j);
            uint4 u;
            u.x = f2tf32(v.x); u.y = f2tf32(v.y); u.z = f2tf32(v.z); u.w = f2tf32(v.w);
            *reinterpret_cast<uint4*>(&sX[st][row][4 * j]) = u;
        }
#pragma unroll
        for (int it = 0; it < 2; ++it) {
            int c   = tid + it * THREADS;
            int nbl = c >> 5;
            int rem = c & 31;
            int ks  = rem >> 4;
            int ch  = rem & 15;
            int nb  = nb0 + nbl;
            bool v  = (nb < NNB);
            const float* src = Wfe + ((size_t)(v ? nb : 0) * NKB + kc0 + ks) * 64 + ch * 4;
            uint32_t dst = (uint32_t)__cvta_generic_to_shared(
                &sW[st][(nbl * 2 + ks) * 64 + ch * 4]);
            cp_async16(dst, src, v ? 16 : 0);
        }
    };

    // Prologue
    load_stage(0, 0);
    asm volatile("cp.async.commit_group;" ::: "memory");
    load_stage(1, 1);
    asm volatile("cp.async.commit_group;" ::: "memory");

    for (int kk = 0; kk < KITERS; ++kk) {
        asm volatile("cp.async.wait_group 1;" ::: "memory");
        __syncthreads();

        int kn = kk + 2;
        if (kn < KITERS) load_stage(kn % STAGES, kn);
        asm volatile("cp.async.commit_group;" ::: "memory");

        const int st = kk % STAGES;
#pragma unroll
        for (int ks = 0; ks < 2; ++ks) {
            const int kb = ks * 8;

            uint32_t af[3][4];
#pragma unroll
            for (int mi = 0; mi < 3; ++mi) {
                int r = wm * 48 + mi * 16 + gid;
                af[mi][0] = __float_as_uint(sX[st][r    ][kb + tig    ]);
                af[mi][1] = __float_as_uint(sX[st][r + 8][kb + tig    ]);
                af[mi][2] = __float_as_uint(sX[st][r    ][kb + tig + 4]);
                af[mi][3] = __float_as_uint(sX[st][r + 8][kb + tig + 4]);
            }
            uint32_t bf[4][2];
#pragma unroll
            for (int ni = 0; ni < 4; ++ni) {
                int nbl = wn * 4 + ni;
                float2 v = *reinterpret_cast<const float2*>(
                    &sW[st][(nbl * 2 + ks) * 64 + lane * 2]);
                bf[ni][0] = __float_as_uint(v.x);
                bf[ni][1] = __float_as_uint(v.y);
            }
#pragma unroll
            for (int mi = 0; mi < 3; ++mi)
#pragma unroll
                for (int ni = 0; ni < 4; ++ni)
                    mma_tf32(acc[mi][ni], af[mi], bf[ni]);
        }
    }

    // ---- epilogue: bias add + guarded float2 stores ----
    float* outb = out + (size_t)b * Tt * Nn;
#pragma unroll
    for (int mi = 0; mi < 3; ++mi) {
        int r0 = m0 + wm * 48 + mi * 16 + gid;
#pragma unroll
        for (int ni = 0; ni < 4; ++ni) {
            int n = n0 + wn * 32 + ni * 8 + tig * 2;
            if (n < Nn) {   // n even, Nn even -> n+1 also valid
                float bv0 = bias[s * Nn + n];
                float bv1 = bias[s * Nn + n + 1];
                if (r0 < Tt) {
                    float2 v = make_float2(acc[mi][ni][0] + bv0, acc[mi][ni][1] + bv1);
                    *reinterpret_cast<float2*>(outb + (size_t)r0 * Nn + n) = v;
                }
                if (r0 + 8 < Tt) {
                    float2 v = make_float2(acc[mi][ni][2] + bv0, acc[mi][ni][3] + bv1);
                    *reinterpret_cast<float2*>(outb + (size_t)(r0 + 8) * Nn + n) = v;
                }
            }
        }
    }
}

extern "C" void kernel_launch(void* const* d_in, const int* in_sizes, int n_in,
                              void* d_out, int out_size) {
    const float* X    = (const float*)d_in[0];
    const void*  subj = d_in[1];
    const float* W    = (const float*)d_in[2];
    const float* bias = (const float*)d_in[3];
    float* out = (float*)d_out;

    probe_subject_kernel<<<1, 32>>>((const unsigned int*)subj);

    int prep_threads = 4 * NNB * NKB * 32;   // 147968
    prep_w_frag<<<(prep_threads + 255) / 256, 256>>>(W);

    dim3 grid((Nn + BN - 1) / BN,   // 3
              (Tt + BM - 1) / BM,   // 3
              Bb);                  // 2048
    subj_gemm_kernel<<<grid, dim3(THREADS)>>>(X, subj, bias, out);
}

// round 4
// speedup vs baseline: 1.0808x; 1.0752x over previous
#include <cuda_runtime.h>
#include <cstdint>

// Problem constants
static constexpr int Bb = 2048, Tt = 281, Kk = 272, Nn = 272;

#define THREADS 192
static constexpr int BM = 96, BN = 96, BK = 16;
static constexpr int STAGES = 4;
static constexpr int XSTR = 20;          // sX row stride (floats): conflict-free + 16B aligned
static constexpr int KITERS = Kk / BK;   // 17, exact
static constexpr int NKB = Kk / 8;       // 34 k8-chunks
static constexpr int NNB = Nn / 8;       // 34 n8-blocks
static constexpr int NBL = BN / 8;       // 12 n-blocks per CTA

// Dynamic smem layout (floats):
//   sX: STAGES * BM * XSTR      = 4 * 1920 = 7680
//   sW: STAGES * NBL*2*64       = 4 * 1536 = 6144
static constexpr int XSTAGE_F = BM * XSTR;       // 1920
static constexpr int WSTAGE_F = NBL * 2 * 64;    // 1536
static constexpr int WBASE_F  = STAGES * XSTAGE_F;
static constexpr int SMEM_BYTES = (WBASE_F + STAGES * WSTAGE_F) * 4;  // 55296

// Fragment-ordered, RNA-pre-rounded weights:
// g_Wf[((e*NNB + nb)*NKB + kc)*64 + lane*2 + {0,1}] = rna(W[e][kc*8+tig+{0,4}][nb*8+gid])
__device__ float g_Wf[4 * NNB * NKB * 64];

// subject dtype flag: 1 if int64, 0 if int32 (jax may demote int64 -> int32)
__device__ int g_subj_is64;

__global__ void probe_subject_kernel(const unsigned int* subj_words) {
    if (threadIdx.x == 0 && blockIdx.x == 0) {
        int is64 = 1;
        for (int i = 1; i < 2048; i += 2)
            if (subj_words[i] != 0u) { is64 = 0; break; }
        g_subj_is64 = is64;
    }
}

__device__ __forceinline__ uint32_t f2tf32(float f) {
    uint32_t u;
    asm("cvt.rna.tf32.f32 %0, %1;" : "=r"(u) : "f"(f));
    return u;
}

// One-time W -> fragment-ordered tf32(RNA) layout
__global__ void prep_w_frag(const float* __restrict__ W) {
    int idx = blockIdx.x * blockDim.x + threadIdx.x;
    if (idx >= 4 * NNB * NKB * 32) return;
    int lane = idx & 31;
    int kc   = (idx >> 5) % NKB;
    int nb   = ((idx >> 5) / NKB) % NNB;
    int e    = (idx >> 5) / (NKB * NNB);
    int gid = lane >> 2, tig = lane & 3;
    int n  = nb * 8 + gid;
    int k0 = kc * 8 + tig;
    const float* We = W + (size_t)e * Kk * Nn;
    float2 v;
    v.x = __uint_as_float(f2tf32(We[(size_t)k0 * Nn + n]));
    v.y = __uint_as_float(f2tf32(We[(size_t)(k0 + 4) * Nn + n]));
    *reinterpret_cast<float2*>(
        &g_Wf[(((size_t)(e * NNB + nb) * NKB + kc) * 32 + lane) * 2]) = v;
}

__device__ __forceinline__ void mma_tf32(float* d, const uint32_t* a, const uint32_t* bfr) {
    asm volatile(
        "mma.sync.aligned.m16n8k8.row.col.f32.tf32.tf32.f32 "
        "{%0,%1,%2,%3}, {%4,%5,%6,%7}, {%8,%9}, {%0,%1,%2,%3};"
        : "+f"(d[0]), "+f"(d[1]), "+f"(d[2]), "+f"(d[3])
        : "r"(a[0]), "r"(a[1]), "r"(a[2]), "r"(a[3]), "r"(bfr[0]), "r"(bfr[1]));
}

__device__ __forceinline__ void cp_async16(uint32_t dst, const void* src, int sz) {
    asm volatile("cp.async.cg.shared.global [%0], [%1], 16, %2;\n"
                 :: "r"(dst), "l"(src), "r"(sz));
}

__global__ __launch_bounds__(THREADS) void subj_gemm_kernel(
    const float* __restrict__ X, const void* __restrict__ subj,
    const float* __restrict__ bias, float* __restrict__ out)
{
    extern __shared__ float smem_f[];

    const int b   = blockIdx.z;
    const int m0  = blockIdx.y * BM;
    const int nb0 = blockIdx.x * NBL;    // n-block origin
    const int n0  = nb0 * 8;

    int s;
    if (g_subj_is64) s = (int)((const long long*)subj)[b];
    else             s = ((const int*)subj)[b];

    const float* Xb  = X + (size_t)b * Tt * Kk;
    const float* Wfe = g_Wf + (size_t)s * NNB * NKB * 64;

    const int tid  = threadIdx.x;
    const int lane = tid & 31;
    const int warp = tid >> 5;     // 0..5
    const int wm   = warp / 3;     // 0..1  (warp rows of 48)
    const int wn   = warp % 3;     // 0..2  (warp cols of 32 = 4 n-blocks)
    const int gid  = lane >> 2;    // 0..7
    const int tig  = lane & 3;     // 0..3

    // Per-thread fixed X-load coordinates (row, j) for both tasks
    const int xrow0 = tid >> 2,                 xj0 = tid & 3;
    const int xrow1 = (tid + THREADS) >> 2,     xj1 = (tid + THREADS) & 3;
    const int xm0 = (m0 + xrow0 < Tt) ? (m0 + xrow0) : (Tt - 1);
    const int xm1 = (m0 + xrow1 < Tt) ? (m0 + xrow1) : (Tt - 1);

    float acc[3][4][4];
#pragma unroll
    for (int i = 0; i < 3; ++i)
#pragma unroll
        for (int j = 0; j < 4; ++j)
#pragma unroll
            for (int k = 0; k < 4; ++k) acc[i][j][k] = 0.f;

    // ---- X: issue LDG.128s for k-chunk ci into regs ----
    auto ldg_x = [&](int ci, float4* xv) {
        const int k0 = ci * BK;
        xv[0] = *reinterpret_cast<const float4*>(Xb + (size_t)xm0 * Kk + k0 + 4 * xj0);
        xv[1] = *reinterpret_cast<const float4*>(Xb + (size_t)xm1 * Kk + k0 + 4 * xj1);
    };
    // ---- X: cvt + STS into stage buffer ----
    auto sts_x = [&](int st, const float4* xv) {
        float* base = smem_f + st * XSTAGE_F;
        uint4 u0, u1;
        u0.x = f2tf32(xv[0].x); u0.y = f2tf32(xv[0].y);
        u0.z = f2tf32(xv[0].z); u0.w = f2tf32(xv[0].w);
        u1.x = f2tf32(xv[1].x); u1.y = f2tf32(xv[1].y);
        u1.z = f2tf32(xv[1].z); u1.w = f2tf32(xv[1].w);
        *reinterpret_cast<uint4*>(base + xrow0 * XSTR + 4 * xj0) = u0;
        *reinterpret_cast<uint4*>(base + xrow1 * XSTR + 4 * xj1) = u1;
    };
    // ---- W: cp.async fragment chunks for k-chunk ci into stage buffer ----
    auto ldw = [&](int st, int ci) {
        const int kc0 = ci * 2;
        float* wbase = smem_f + WBASE_F + st * WSTAGE_F;
#pragma unroll
        for (int it = 0; it < 2; ++it) {
            int c   = tid + it * THREADS;
            int nbl = c >> 5;
            int rem = c & 31;
            int ks  = rem >> 4;
            int ch  = rem & 15;
            int nb  = nb0 + nbl;
            bool v  = (nb < NNB);
            const float* src = Wfe + ((size_t)(v ? nb : 0) * NKB + kc0 + ks) * 64 + ch * 4;
            uint32_t dst = (uint32_t)__cvta_generic_to_shared(
                wbase + (nbl * 2 + ks) * 64 + ch * 4);
            cp_async16(dst, src, v ? 16 : 0);
        }
    };

    // ---- prologue: stages 0,1 fully; stage 2 W async + X held in regs ----
    float4 xv[2], xvP[2];
    ldg_x(0, xv); sts_x(0, xv);
    ldw(0, 0);
    asm volatile("cp.async.commit_group;" ::: "memory");
    ldg_x(1, xv); sts_x(1, xv);
    ldw(1, 1);
    asm volatile("cp.async.commit_group;" ::: "memory");
    ldg_x(2, xvP);               // STS happens at iter 0
    ldw(2, 2);
    asm volatile("cp.async.commit_group;" ::: "memory");

    for (int kk = 0; kk < KITERS; ++kk) {
        asm volatile("cp.async.wait_group 2;" ::: "memory");
        __syncthreads();

        // STS X regs (loaded last iter / prologue) for stage kk+2
        const int s2 = kk + 2;
        if (s2 < KITERS) sts_x(s2 % STAGES, xvP);
        // Issue X LDG + W cp.async for stage kk+3
        const int s3 = kk + 3;
        if (s3 < KITERS) {
            ldg_x(s3, xvP);
            ldw(s3 % STAGES, s3);
        }
        asm volatile("cp.async.commit_group;" ::: "memory");

        // ---- compute stage kk ----
        const int st = kk % STAGES;
        const float* xbase = smem_f + st * XSTAGE_F;
        const float* wbase = smem_f + WBASE_F + st * WSTAGE_F;
#pragma unroll
        for (int ks = 0; ks < 2; ++ks) {
            const int kb = ks * 8;

            uint32_t af[3][4];
#pragma unroll
            for (int mi = 0; mi < 3; ++mi) {
                int r = wm * 48 + mi * 16 + gid;
                af[mi][0] = __float_as_uint(xbase[(r    ) * XSTR + kb + tig    ]);
                af[mi][1] = __float_as_uint(xbase[(r + 8) * XSTR + kb + tig    ]);
                af[mi][2] = __float_as_uint(xbase[(r    ) * XSTR + kb + tig + 4]);
                af[mi][3] = __float_as_uint(xbase[(r + 8) * XSTR + kb + tig + 4]);
            }
            uint32_t bf[4][2];
#pragma unroll
            for (int ni = 0; ni < 4; ++ni) {
                int nbl = wn * 4 + ni;
                float2 v = *reinterpret_cast<const float2*>(
                    wbase + (nbl * 2 + ks) * 64 + lane * 2);
                bf[ni][0] = __float_as_uint(v.x);
                bf[ni][1] = __float_as_uint(v.y);
            }
#pragma unroll
            for (int mi = 0; mi < 3; ++mi)
#pragma unroll
                for (int ni = 0; ni < 4; ++ni)
                    mma_tf32(acc[mi][ni], af[mi], bf[ni]);
        }
    }

    // ---- epilogue: bias add + guarded float2 stores ----
    float* outb = out + (size_t)b * Tt * Nn;
#pragma unroll
    for (int mi = 0; mi < 3; ++mi) {
        int r0 = m0 + wm * 48 + mi * 16 + gid;
#pragma unroll
        for (int ni = 0; ni < 4; ++ni) {
            int n = n0 + wn * 32 + ni * 8 + tig * 2;
            if (n < Nn) {   // n even, Nn even -> n+1 also valid
                float bv0 = bias[s * Nn + n];
                float bv1 = bias[s * Nn + n + 1];
                if (r0 < Tt) {
                    float2 v = make_float2(acc[mi][ni][0] + bv0, acc[mi][ni][1] + bv1);
                    *reinterpret_cast<float2*>(outb + (size_t)r0 * Nn + n) = v;
                }
                if (r0 + 8 < Tt) {
                    float2 v = make_float2(acc[mi][ni][2] + bv0, acc[mi][ni][3] + bv1);
                    *reinterpret_cast<float2*>(outb + (size_t)(r0 + 8) * Nn + n) = v;
                }
            }
        }
    }
}

extern "C" void kernel_launch(void* const* d_in, const int* in_sizes, int n_in,
                              void* d_out, int out_size) {
    const float* X    = (const float*)d_in[0];
    const void*  subj = d_in[1];
    const float* W    = (const float*)d_in[2];
    const float* bias = (const float*)d_in[3];
    float* out = (float*)d_out;

    cudaFuncSetAttribute(subj_gemm_kernel,
                         cudaFuncAttributeMaxDynamicSharedMemorySize, SMEM_BYTES);

    probe_subject_kernel<<<1, 32>>>((const unsigned int*)subj);

    int prep_threads = 4 * NNB * NKB * 32;   // 147968
    prep_w_frag<<<(prep_threads + 255) / 256, 256>>>(W);

    dim3 grid((Nn + BN - 1) / BN,   // 3
              (Tt + BM - 1) / BM,   // 3
              Bb);                  // 2048
    subj_gemm_kernel<<<grid, dim3(THREADS), SMEM_BYTES>>>(X, subj, bias, out);
}